// round 4
// baseline (speedup 1.0000x reference)
#include <cuda_runtime.h>
#include <cuda_bf16.h>
#include <math.h>

// ---------------------------------------------------------------------------
// HPNETLoss — single fused kernel, one-wave persistent grid, 4-way batched
// streaming loads for high MLP.
//   out[0] = sum(weight * (confidence - confidence_gt)^2) / 65536   (16.7M elems)
//   out[1] = sum(mask * (dr[:,0]-ann[:,0])^2) / N                   (N=8192)
//   out[2] = sum(mask * min(||Mgt-Mp||F, ||Mgt-Mp@RY||F)) / N
// ---------------------------------------------------------------------------

#define BT 256
#define GB 444            // 148 SMs * 3 blocks -> exactly one wave at ~80 regs

__device__ float        g_scratch[3];   // self-resetting accumulators
__device__ unsigned int g_count;        // wraps to 0 via atomicInc

__device__ __forceinline__ float block_reduce(float v, float* warp_sums) {
    int lane = threadIdx.x & 31;
    int wid  = threadIdx.x >> 5;
    #pragma unroll
    for (int off = 16; off > 0; off >>= 1)
        v += __shfl_down_sync(0xFFFFFFFFu, v, off);
    if (lane == 0) warp_sums[wid] = v;
    __syncthreads();
    v = (threadIdx.x < (BT / 32)) ? warp_sums[threadIdx.x] : 0.0f;
    if (wid == 0) {
        #pragma unroll
        for (int off = 16; off > 0; off >>= 1)
            v += __shfl_down_sync(0xFFFFFFFFu, v, off);
    }
    __syncthreads();
    return v;
}

__device__ __forceinline__ void quat2mat(float q0, float q1, float q2, float q3,
                                         float m[9]) {
    m[0] = q0*q0 + q1*q1 - q2*q2 - q3*q3;
    m[1] = 2.0f * (q1*q2 - q0*q3);
    m[2] = 2.0f * (q1*q3 + q0*q2);
    m[3] = 2.0f * (q1*q2 + q0*q3);
    m[4] = q0*q0 - q1*q1 + q2*q2 - q3*q3;
    m[5] = 2.0f * (q2*q3 - q0*q1);
    m[6] = 2.0f * (q1*q3 - q0*q2);
    m[7] = 2.0f * (q2*q3 + q0*q1);
    m[8] = q0*q0 - q1*q1 - q2*q2 + q3*q3;
}

__device__ __forceinline__ float wsq(float w, float c, float g, float acc) {
    float d = c - g;
    return fmaf(w * d, d, acc);
}

__device__ __forceinline__ float wsq4(float4 w, float4 c, float4 g, float acc) {
    acc = wsq(w.x, c.x, g.x, acc);
    acc = wsq(w.y, c.y, g.y, acc);
    acc = wsq(w.z, c.z, g.z, acc);
    acc = wsq(w.w, c.w, g.w, acc);
    return acc;
}

__global__ __launch_bounds__(BT)
void hpnet_loss_fused(const float4* __restrict__ conf,
                      const float4* __restrict__ gt,
                      const float4* __restrict__ wgt,
                      const float*  __restrict__ dr,
                      const float*  __restrict__ ann,
                      const int*    __restrict__ flags,
                      float* __restrict__ out,
                      unsigned n4, int N) {
    __shared__ float warp_sums[BT / 32];

    const unsigned gid    = blockIdx.x * BT + threadIdx.x;
    const unsigned stride = GB * BT;

    // ---- ann loss (gid < 8192 only; trivially hidden)
    float dpart = 0.0f, rpart = 0.0f;
    for (unsigned i = gid; i < (unsigned)N; i += stride) {
        if (flags[i] != 0) {
            float dd = dr[i*5 + 0] - ann[i*5 + 0];
            dpart += dd * dd;

            float mp[9];
            quat2mat(ann[i*5+1], ann[i*5+2], ann[i*5+3], ann[i*5+4], mp);

            float q0 = dr[i*5+1], q1 = dr[i*5+2], q2 = dr[i*5+3], q3 = dr[i*5+4];
            float inv = rsqrtf(q0*q0 + q1*q1 + q2*q2 + q3*q3);
            float mg[9];
            quat2mat(q0*inv, q1*inv, q2*inv, q3*inv, mg);

            // RY = diag(-1,1,-1): columns 0,2 of mp negated for the second norm
            float s1 = 0.0f, s2 = 0.0f;
            #pragma unroll
            for (int r = 0; r < 3; ++r) {
                float e0 = mg[r*3+0] - mp[r*3+0];
                float e1 = mg[r*3+1] - mp[r*3+1];
                float e2 = mg[r*3+2] - mp[r*3+2];
                s1 += e0*e0 + e1*e1 + e2*e2;
                float f0 = mg[r*3+0] + mp[r*3+0];
                float f1 = mg[r*3+1] - mp[r*3+1];
                float f2 = mg[r*3+2] + mp[r*3+2];
                s2 += f0*f0 + f1*f1 + f2*f2;
            }
            rpart += sqrtf(fminf(s1, s2));
        }
    }

    // ---- confidence loss: 4-way batched streaming (12 LDG.128 in flight)
    float a0 = 0.0f, a1 = 0.0f, a2 = 0.0f, a3 = 0.0f;
    unsigned i = gid;
    while (i + 3u * stride < n4) {
        unsigned i1 = i + stride, i2 = i + 2u*stride, i3 = i + 3u*stride;
        float4 c0 = conf[i], c1 = conf[i1], c2 = conf[i2], c3 = conf[i3];
        float4 g0 = gt[i],   g1 = gt[i1],   g2 = gt[i2],   g3 = gt[i3];
        float4 w0 = wgt[i],  w1 = wgt[i1],  w2 = wgt[i2],  w3 = wgt[i3];
        a0 = wsq4(w0, c0, g0, a0);
        a1 = wsq4(w1, c1, g1, a1);
        a2 = wsq4(w2, c2, g2, a2);
        a3 = wsq4(w3, c3, g3, a3);
        i += 4u * stride;
    }
    for (; i < n4; i += stride) {
        float4 c = conf[i];
        float4 g = gt[i];
        float4 w = wgt[i];
        a0 = wsq4(w, c, g, a0);
    }
    float acc = (a0 + a1) + (a2 + a3);

    // ---- block reductions + completion
    float csum = block_reduce(acc,   warp_sums);
    float dsum = block_reduce(dpart, warp_sums);
    float rsum = block_reduce(rpart, warp_sums);

    if (threadIdx.x == 0) {
        if (csum != 0.0f) atomicAdd(&g_scratch[0], csum);
        if (dsum != 0.0f) atomicAdd(&g_scratch[1], dsum);
        if (rsum != 0.0f) atomicAdd(&g_scratch[2], rsum);
        __threadfence();
        unsigned int ticket = atomicInc(&g_count, GB - 1);
        if (ticket == GB - 1) {
            float s0 = atomicExch(&g_scratch[0], 0.0f);
            float s1 = atomicExch(&g_scratch[1], 0.0f);
            float s2 = atomicExch(&g_scratch[2], 0.0f);
            float invN = 1.0f / (float)N;
            out[0] = s0 * (1.0f / 65536.0f);
            out[1] = s1 * invN;
            out[2] = s2 * invN;
        }
    }
}

extern "C" void kernel_launch(void* const* d_in, const int* in_sizes, int n_in,
                              void* d_out, int out_size) {
    const float* conf = (const float*)d_in[0];
    const float* gt   = (const float*)d_in[1];
    const float* wgt  = (const float*)d_in[2];
    const float* dr   = (const float*)d_in[3];
    const float* ann  = (const float*)d_in[4];
    const int*   flags = (const int*)d_in[5];
    float* out = (float*)d_out;

    unsigned n4 = (unsigned)(in_sizes[0] / 4);   // 4,194,304 float4s
    int N = in_sizes[5];                         // 8192

    hpnet_loss_fused<<<GB, BT>>>(
        (const float4*)conf, (const float4*)gt, (const float4*)wgt,
        dr, ann, flags, out, n4, N);
}

// round 5
// speedup vs baseline: 1.0522x; 1.0522x over previous
#include <cuda_runtime.h>
#include <cuda_bf16.h>
#include <math.h>

// ---------------------------------------------------------------------------
// HPNETLoss — single fused kernel. Streaming loads use __ldcs (evict-first)
// since every byte is read exactly once; counted+unrolled main loop.
//   out[0] = sum(weight * (confidence - confidence_gt)^2) / 65536   (16.7M)
//   out[1] = sum(mask * (dr[:,0]-ann[:,0])^2) / N                   (N=8192)
//   out[2] = sum(mask * min(||Mgt-Mp||F, ||Mgt-Mp@RY||F)) / N
// ---------------------------------------------------------------------------

#define BT 256
#define GB 1184           // 148 SMs * 8 blocks

__device__ float        g_scratch[3];   // self-resetting accumulators
__device__ unsigned int g_count;        // wraps to 0 via atomicInc

__device__ __forceinline__ float block_reduce(float v, float* warp_sums) {
    int lane = threadIdx.x & 31;
    int wid  = threadIdx.x >> 5;
    #pragma unroll
    for (int off = 16; off > 0; off >>= 1)
        v += __shfl_down_sync(0xFFFFFFFFu, v, off);
    if (lane == 0) warp_sums[wid] = v;
    __syncthreads();
    v = (threadIdx.x < (BT / 32)) ? warp_sums[threadIdx.x] : 0.0f;
    if (wid == 0) {
        #pragma unroll
        for (int off = 16; off > 0; off >>= 1)
            v += __shfl_down_sync(0xFFFFFFFFu, v, off);
    }
    __syncthreads();
    return v;
}

__device__ __forceinline__ void quat2mat(float q0, float q1, float q2, float q3,
                                         float m[9]) {
    m[0] = q0*q0 + q1*q1 - q2*q2 - q3*q3;
    m[1] = 2.0f * (q1*q2 - q0*q3);
    m[2] = 2.0f * (q1*q3 + q0*q2);
    m[3] = 2.0f * (q1*q2 + q0*q3);
    m[4] = q0*q0 - q1*q1 + q2*q2 - q3*q3;
    m[5] = 2.0f * (q2*q3 - q0*q1);
    m[6] = 2.0f * (q1*q3 - q0*q2);
    m[7] = 2.0f * (q2*q3 + q0*q1);
    m[8] = q0*q0 - q1*q1 - q2*q2 + q3*q3;
}

__device__ __forceinline__ float wsq4(float4 w, float4 c, float4 g, float acc) {
    float d0 = c.x - g.x;
    float d1 = c.y - g.y;
    float d2 = c.z - g.z;
    float d3 = c.w - g.w;
    acc = fmaf(w.x * d0, d0, acc);
    acc = fmaf(w.y * d1, d1, acc);
    acc = fmaf(w.z * d2, d2, acc);
    acc = fmaf(w.w * d3, d3, acc);
    return acc;
}

__global__ __launch_bounds__(BT)
void hpnet_loss_fused(const float4* __restrict__ conf,
                      const float4* __restrict__ gt,
                      const float4* __restrict__ wgt,
                      const float*  __restrict__ dr,
                      const float*  __restrict__ ann,
                      const int*    __restrict__ flags,
                      float* __restrict__ out,
                      unsigned n4, int N) {
    __shared__ float warp_sums[BT / 32];

    const unsigned gid    = blockIdx.x * BT + threadIdx.x;
    const unsigned stride = GB * BT;     // 303,104

    // ---- ann loss (gid < 8192 only; hidden under the stream)
    float dpart = 0.0f, rpart = 0.0f;
    if (gid < (unsigned)N) {
        unsigned i = gid;
        if (flags[i] != 0) {
            float dd = dr[i*5 + 0] - ann[i*5 + 0];
            dpart = dd * dd;

            float mp[9];
            quat2mat(ann[i*5+1], ann[i*5+2], ann[i*5+3], ann[i*5+4], mp);

            float q0 = dr[i*5+1], q1 = dr[i*5+2], q2 = dr[i*5+3], q3 = dr[i*5+4];
            float inv = rsqrtf(q0*q0 + q1*q1 + q2*q2 + q3*q3);
            float mg[9];
            quat2mat(q0*inv, q1*inv, q2*inv, q3*inv, mg);

            // RY = diag(-1,1,-1): columns 0,2 of mp negated for the second norm
            float s1 = 0.0f, s2 = 0.0f;
            #pragma unroll
            for (int r = 0; r < 3; ++r) {
                float e0 = mg[r*3+0] - mp[r*3+0];
                float e1 = mg[r*3+1] - mp[r*3+1];
                float e2 = mg[r*3+2] - mp[r*3+2];
                s1 += e0*e0 + e1*e1 + e2*e2;
                float f0 = mg[r*3+0] + mp[r*3+0];
                float f1 = mg[r*3+1] - mp[r*3+1];
                float f2 = mg[r*3+2] + mp[r*3+2];
                s2 += f0*f0 + f1*f1 + f2*f2;
            }
            rpart = sqrtf(fminf(s1, s2));
        }
    }

    // ---- confidence loss: counted main loop, evict-streaming loads
    const unsigned full_iters = n4 / stride;   // uniform across threads
    float acc = 0.0f;
    unsigned i = gid;
    #pragma unroll 4
    for (unsigned k = 0; k < full_iters; ++k, i += stride) {
        float4 c = __ldcs(&conf[i]);
        float4 g = __ldcs(&gt[i]);
        float4 w = __ldcs(&wgt[i]);
        acc = wsq4(w, c, g, acc);
    }
    if (i < n4) {   // at most one remainder iteration per thread
        float4 c = __ldcs(&conf[i]);
        float4 g = __ldcs(&gt[i]);
        float4 w = __ldcs(&wgt[i]);
        acc = wsq4(w, c, g, acc);
    }

    // ---- block reductions + completion
    float csum = block_reduce(acc,   warp_sums);
    float dsum = block_reduce(dpart, warp_sums);
    float rsum = block_reduce(rpart, warp_sums);

    if (threadIdx.x == 0) {
        if (csum != 0.0f) atomicAdd(&g_scratch[0], csum);
        if (dsum != 0.0f) atomicAdd(&g_scratch[1], dsum);
        if (rsum != 0.0f) atomicAdd(&g_scratch[2], rsum);
        __threadfence();
        unsigned int ticket = atomicInc(&g_count, GB - 1);
        if (ticket == GB - 1) {
            float s0 = atomicExch(&g_scratch[0], 0.0f);
            float s1 = atomicExch(&g_scratch[1], 0.0f);
            float s2 = atomicExch(&g_scratch[2], 0.0f);
            float invN = 1.0f / (float)N;
            out[0] = s0 * (1.0f / 65536.0f);
            out[1] = s1 * invN;
            out[2] = s2 * invN;
        }
    }
}

extern "C" void kernel_launch(void* const* d_in, const int* in_sizes, int n_in,
                              void* d_out, int out_size) {
    const float* conf = (const float*)d_in[0];
    const float* gt   = (const float*)d_in[1];
    const float* wgt  = (const float*)d_in[2];
    const float* dr   = (const float*)d_in[3];
    const float* ann  = (const float*)d_in[4];
    const int*   flags = (const int*)d_in[5];
    float* out = (float*)d_out;

    unsigned n4 = (unsigned)(in_sizes[0] / 4);   // 4,194,304 float4s
    int N = in_sizes[5];                         // 8192

    hpnet_loss_fused<<<GB, BT>>>(
        (const float4*)conf, (const float4*)gt, (const float4*)wgt,
        dr, ann, flags, out, n4, N);
}